// round 14
// baseline (speedup 1.0000x reference)
#include <cuda_runtime.h>
#include <cuda_bf16.h>
#include <math.h>
#include <stdint.h>

#define B_  32
#define TE_ 8192
#define H_  128
#define NTILE 2048            // (B_*TE_)/128 tiles of 128 timesteps
#define TPB   64              // tiles per batch

// ---------------- device scratch ----------------
__device__ float g_Uh[B_ * H_];
__device__ float g_tmax[NTILE];            // per-tile max
__device__ float g_tsum[NTILE];            // per-tile sum(exp(s - tmax))
__device__ float g_cpart[NTILE * H_];      // exp-weighted partial contexts
__device__ __nv_bfloat16 g_WhiT[H_ * H_];  // W^T split-high [n][h]
__device__ __nv_bfloat16 g_WloT[H_ * H_];  // W^T split-low  [n][h]
__device__ int g_ticket;                   // work-stealing ticket (reset by k01)

// ---------------- helpers ----------------
__device__ __forceinline__ uint32_t smem_u32(const void* p) {
    uint32_t a;
    asm("{ .reg .u64 t; cvta.to.shared.u64 t, %1; cvt.u32.u64 %0, t; }" : "=r"(a) : "l"(p));
    return a;
}
__device__ __forceinline__ void ldsm_x4(uint32_t& r0, uint32_t& r1, uint32_t& r2,
                                        uint32_t& r3, uint32_t addr) {
    asm volatile("ldmatrix.sync.aligned.m8n8.x4.shared.b16 {%0,%1,%2,%3}, [%4];"
                 : "=r"(r0), "=r"(r1), "=r"(r2), "=r"(r3) : "r"(addr));
}
__device__ __forceinline__ void mma_bf16(float* c, uint32_t a0, uint32_t a1,
                                         uint32_t a2, uint32_t a3,
                                         uint32_t b0, uint32_t b1) {
    asm volatile(
        "mma.sync.aligned.m16n8k16.row.col.f32.bf16.bf16.f32 "
        "{%0,%1,%2,%3}, {%4,%5,%6,%7}, {%8,%9}, {%0,%1,%2,%3};"
        : "+f"(c[0]), "+f"(c[1]), "+f"(c[2]), "+f"(c[3])
        : "r"(a0), "r"(a1), "r"(a2), "r"(a3), "r"(b0), "r"(b1));
}
__device__ __forceinline__ float tanh_approx(float x) {
    float y;
    asm("tanh.approx.f32 %0, %1;" : "=f"(y) : "f"(x));
    return y;
}
#define CP_ASYNC16(dst, src) \
    asm volatile("cp.async.cg.shared.global [%0], [%1], 16;" :: "r"(dst), "l"(src))
#define CP_COMMIT()  asm volatile("cp.async.commit_group;" ::: "memory")
#define CP_WAIT0()   asm volatile("cp.async.wait_group 0;" ::: "memory")

// pack hi16(a),hi16(b) -> {lo=a.hi, hi=b.hi}
__device__ __forceinline__ uint32_t prmt_hi(uint32_t a, uint32_t b) {
    uint32_t d;
    asm("prmt.b32 %0, %1, %2, 0x7632;" : "=r"(d) : "r"(a), "r"(b));
    return d;
}
// pack bf16(lo0) into low half, bf16(lo1) into high half
__device__ __forceinline__ uint32_t cvt_bf16x2(float lo1, float lo0) {
    uint32_t d;
    asm("cvt.rn.bf16x2.f32 %0, %1, %2;" : "=r"(d) : "f"(lo1), "f"(lo0));
    return d;
}

// ---------------- K01: W^T hi/lo split + Uh + ticket reset ----------------
__global__ void k01_prep(const float* __restrict__ W, const float* __restrict__ dec,
                         const float* __restrict__ U, int k2grid) {
    int bid = blockIdx.x, tid = threadIdx.x;
    if (bid == 0 && tid == 0) g_ticket = k2grid;
    if (bid < 64) {
        int idx = bid * 256 + tid;          // 16384 total
        int k = idx >> 7, h = idx & 127;
        float x = W[h * H_ + k];
        __nv_bfloat16 hi = __float2bfloat16(x);
        __nv_bfloat16 lo = __float2bfloat16(x - __bfloat162float(hi));
        g_WhiT[k * H_ + h] = hi;
        g_WloT[k * H_ + h] = lo;
    } else {
        __shared__ float d_s[2][H_];
        int half = tid >> 7, k = tid & 127;
        int b = (bid - 64) * 2 + half;
        d_s[half][k] = dec[b * H_ + k];
        __syncthreads();
        float acc = 0.f;
#pragma unroll 16
        for (int h = 0; h < H_; ++h) acc = fmaf(d_s[half][h], U[h * H_ + k], acc);
        g_Uh[b * H_ + k] = acc;
    }
}

// ---------------- K2: persistent fused GEMM + tanh·V + online softmax + context ----------------
#define RSTR     272                      // 128 bf16 + 8 pad = 272 B rows
#define TILE_B   (128 * RSTR)             // 34816
#define OFF_UH   0
#define OFF_V    512
#define OFF_EPI  1024                     // 2 x 128 floats
#define OFF_SW   2048                     // 128 floats
#define OFF_RED  2560                     // 8 floats
#define OFF_CP   2624                     // 8 x 128 floats = 4096 B
#define OFF_AHI  6784
#define OFF_ALO  (OFF_AHI + TILE_B)
#define OFF_BHI  (OFF_ALO + TILE_B)
#define OFF_BLO  (OFF_BHI + TILE_B)
#define OFF_STG  (OFF_BLO + TILE_B)       // fp32 stage, 64 KB
#define K2_SMEM  (OFF_STG + 65536)        // 211584 B

__global__ void __launch_bounds__(512, 1)
k2_scores(const float* __restrict__ enc, const float* __restrict__ V,
          float* __restrict__ scores) {
    extern __shared__ char sm[];
    uint32_t base = smem_u32(sm);

    int tid  = threadIdx.x;
    int wid  = tid >> 5;
    int lane = tid & 31;

    float* uh_s = (float*)(sm + OFF_UH);
    float* v_s  = (float*)(sm + OFF_V);
    float* epi  = (float*)(sm + OFF_EPI);
    float* swm  = (float*)(sm + OFF_SW);
    float* red  = (float*)(sm + OFF_RED);
    float* cp   = (float*)(sm + OFF_CP);

    if (tid < 128) v_s[tid] = V[tid];

    // W tiles: loaded ONCE per CTA
#pragma unroll
    for (int i = 0; i < 8; ++i) {
        int g = i * 512 + tid;
        int row = g >> 5, c = g & 31;
        int off = row * RSTR + c * 8;
        *(uint2*)(sm + OFF_BHI + off) = *(const uint2*)(g_WhiT + row * 128 + c * 4);
        *(uint2*)(sm + OFF_BLO + off) = *(const uint2*)(g_WloT + row * 128 + c * 4);
    }

    int wy = wid & 7, wx = wid >> 3;
    uint32_t aOff = (uint32_t)((lane & 15) * RSTR + (lane >> 4) * 16);
    uint32_t bOff = (uint32_t)(((lane & 7) + ((lane >> 4) << 3)) * RSTR + (((lane >> 3) & 1) << 4));
    uint32_t aHi = base + OFF_AHI + wy * 16 * RSTR + aOff;
    uint32_t aLo = base + OFF_ALO + wy * 16 * RSTR + aOff;
    uint32_t bHi = base + OFF_BHI + wx * 64 * RSTR + bOff;
    uint32_t bLo = base + OFF_BLO + wx * 64 * RSTR + bOff;
    uint32_t stg = base + OFF_STG + tid * 16;

    int T = blockIdx.x;
    if (T < NTILE) {
        const float4* encT = (const float4*)(enc + (size_t)T * 128 * H_);
#pragma unroll
        for (int i = 0; i < 8; ++i)
            CP_ASYNC16(stg + i * 8192, encT + i * 512 + tid);
        CP_COMMIT();
    }
    __shared__ int s_next;

    while (T < NTILE) {
        int b = T >> 6;

        CP_WAIT0();
        __syncthreads();   // stage ready; A tiles free

        // convert staged fp32 -> bf16 hi(trunc)/lo A tiles (PRMT + FSUB + CVT.bf16x2)
#pragma unroll
        for (int i = 0; i < 8; ++i) {
            int g = i * 512 + tid;
            int row = g >> 5, c4 = g & 31;
            float4 ff = *(const float4*)(sm + OFF_STG + (size_t)g * 16);
            uint32_t x0 = __float_as_uint(ff.x), x1 = __float_as_uint(ff.y);
            uint32_t x2 = __float_as_uint(ff.z), x3 = __float_as_uint(ff.w);
            uint2 hp, lp;
            hp.x = prmt_hi(x0, x1);
            hp.y = prmt_hi(x2, x3);
            float l0 = ff.x - __uint_as_float(x0 & 0xFFFF0000u);
            float l1 = ff.y - __uint_as_float(x1 & 0xFFFF0000u);
            float l2 = ff.z - __uint_as_float(x2 & 0xFFFF0000u);
            float l3 = ff.w - __uint_as_float(x3 & 0xFFFF0000u);
            lp.x = cvt_bf16x2(l1, l0);
            lp.y = cvt_bf16x2(l3, l2);
            int off = row * RSTR + c4 * 8;
            *(uint2*)(sm + OFF_AHI + off) = hp;
            *(uint2*)(sm + OFF_ALO + off) = lp;
        }
        if (tid < 128) uh_s[tid] = g_Uh[b * 128 + tid];
        if (tid == 0) s_next = atomicAdd(&g_ticket, 1);
        __syncthreads();   // A ready; stage free; s_next visible

        // prefetch NEXT tile into stage (hidden behind MMA + epilogue)
        int Tn = s_next;
        if (Tn < NTILE) {
            const float4* encT = (const float4*)(enc + (size_t)Tn * 128 * H_);
#pragma unroll
            for (int i = 0; i < 8; ++i)
                CP_ASYNC16(stg + i * 8192, encT + i * 512 + tid);
        }
        CP_COMMIT();

        // ---- MMA: 16 rows x 64 cols per warp, 3-term split-bf16
        float c[8][4];
#pragma unroll
        for (int n = 0; n < 8; ++n)
#pragma unroll
            for (int j = 0; j < 4; ++j) c[n][j] = 0.f;

#pragma unroll
        for (int k = 0; k < 8; ++k) {
            uint32_t kb = k * 32;
            uint32_t bh[4][4], bl[4][4];
#pragma unroll
            for (int p = 0; p < 4; ++p) {
                ldsm_x4(bh[p][0], bh[p][1], bh[p][2], bh[p][3], bHi + p * 16 * RSTR + kb);
                ldsm_x4(bl[p][0], bl[p][1], bl[p][2], bl[p][3], bLo + p * 16 * RSTR + kb);
            }
            uint32_t ah0, ah1, ah2, ah3, al0, al1, al2, al3;
            ldsm_x4(ah0, ah1, ah2, ah3, aHi + kb);
            ldsm_x4(al0, al1, al2, al3, aLo + kb);
#pragma unroll
            for (int p = 0; p < 4; ++p) {
                mma_bf16(c[2 * p],     ah0, ah1, ah2, ah3, bh[p][0], bh[p][1]);
                mma_bf16(c[2 * p + 1], ah0, ah1, ah2, ah3, bh[p][2], bh[p][3]);
                mma_bf16(c[2 * p],     ah0, ah1, ah2, ah3, bl[p][0], bl[p][1]);
                mma_bf16(c[2 * p + 1], ah0, ah1, ah2, ah3, bl[p][2], bl[p][3]);
                mma_bf16(c[2 * p],     al0, al1, al2, al3, bh[p][0], bh[p][1]);
                mma_bf16(c[2 * p + 1], al0, al1, al2, al3, bh[p][2], bh[p][3]);
            }
        }

        // ---- epilogue: s[t] = sum_n v[n] * tanh(y + uh[n])
        {
            int qid = lane >> 2;
            int npair = (lane & 3) * 2;
            float s0 = 0.f, s1 = 0.f;
#pragma unroll
            for (int nt = 0; nt < 8; ++nt) {
                int n = wx * 64 + nt * 8 + npair;
                float vn0 = v_s[n], vn1 = v_s[n + 1];
                float u0 = uh_s[n], u1 = uh_s[n + 1];
                s0 += vn0 * tanh_approx(c[nt][0] + u0) + vn1 * tanh_approx(c[nt][1] + u1);
                s1 += vn0 * tanh_approx(c[nt][2] + u0) + vn1 * tanh_approx(c[nt][3] + u1);
            }
            s0 += __shfl_xor_sync(0xffffffffu, s0, 1);
            s0 += __shfl_xor_sync(0xffffffffu, s0, 2);
            s1 += __shfl_xor_sync(0xffffffffu, s1, 1);
            s1 += __shfl_xor_sync(0xffffffffu, s1, 2);
            if ((lane & 3) == 0) {
                int r = wy * 16 + qid;
                epi[wx * 128 + r]     = s0;
                epi[wx * 128 + r + 8] = s1;
            }
        }
        __syncthreads();

        // ---- tile softmax stats
        float sv = 0.f;
        if (tid < 128) {
            sv = epi[tid] + epi[128 + tid];
            scores[(size_t)T * 128 + tid] = sv;
            float m = sv;
#pragma unroll
            for (int msk = 16; msk; msk >>= 1) m = fmaxf(m, __shfl_xor_sync(0xffffffffu, m, msk));
            if (lane == 0) red[wid] = m;
        }
        __syncthreads();
        float mt = fmaxf(fmaxf(red[0], red[1]), fmaxf(red[2], red[3]));
        if (tid < 128) {
            float w = __expf(sv - mt);
            swm[tid] = w;
#pragma unroll
            for (int msk = 16; msk; msk >>= 1) w += __shfl_xor_sync(0xffffffffu, w, msk);
            if (lane == 0) red[4 + wid] = w;
        }
        __syncthreads();
        if (tid == 0) {
            g_tmax[T] = mt;
            g_tsum[T] = red[4] + red[5] + red[6] + red[7];
        }

        // ---- partial context: bf16x2 paired loads, 8 t-slices of 16
        {
            int hp2 = tid & 63;               // h-pair index
            int sl  = tid >> 6;               // slice 0..7
            const char* pH = sm + OFF_AHI + (sl * 16) * RSTR + hp2 * 4;
            const char* pL = sm + OFF_ALO + (sl * 16) * RSTR + hp2 * 4;
            float ax = 0.f, ay = 0.f;
#pragma unroll
            for (int t = 0; t < 16; ++t) {
                __nv_bfloat162 hv = *(const __nv_bfloat162*)(pH + t * RSTR);
                __nv_bfloat162 lv = *(const __nv_bfloat162*)(pL + t * RSTR);
                float2 hf = __bfloat1622float2(hv);
                float2 lf = __bfloat1622float2(lv);
                float w = swm[sl * 16 + t];
                ax = fmaf(w, hf.x + lf.x, ax);
                ay = fmaf(w, hf.y + lf.y, ay);
            }
            cp[sl * 128 + hp2 * 2]     = ax;
            cp[sl * 128 + hp2 * 2 + 1] = ay;
        }
        __syncthreads();
        if (tid < 128) {
            float s = 0.f;
#pragma unroll
            for (int sl = 0; sl < 8; ++sl) s += cp[sl * 128 + tid];
            g_cpart[(size_t)T * 128 + tid] = s;
        }

        T = Tn;
    }
}

// ---------------- batch stats helper (warp 0 computes mm, inv) ----------------
__device__ __forceinline__ void batch_stats(int b, int tid, float* s_out) {
    if (tid < 32) {
        float m0 = g_tmax[b * TPB + tid], m1 = g_tmax[b * TPB + 32 + tid];
        float mm = fmaxf(m0, m1);
#pragma unroll
        for (int msk = 16; msk; msk >>= 1) mm = fmaxf(mm, __shfl_xor_sync(0xffffffffu, mm, msk));
        float s = g_tsum[b * TPB + tid] * __expf(m0 - mm)
                + g_tsum[b * TPB + 32 + tid] * __expf(m1 - mm);
#pragma unroll
        for (int msk = 16; msk; msk >>= 1) s += __shfl_xor_sync(0xffffffffu, s, msk);
        if (tid == 0) { s_out[0] = mm; s_out[1] = 1.f / s; }
    }
}

// ---------------- K45: blocks 0..127 normalize e; blocks 128..159 reduce contexts ----------------
__global__ void __launch_bounds__(512)
k45_final(float* __restrict__ e_out, float* __restrict__ c_out) {
    __shared__ float st[2];
    __shared__ float sc[TPB];
    __shared__ float cpz[4 * 128];
    int blk = blockIdx.x, tid = threadIdx.x;

    if (blk < 128) {
        int b = blk >> 2;
        batch_stats(b, tid, st);
        __syncthreads();
        float mm = st[0], inv = st[1];
        float4* p = (float4*)(e_out + (size_t)b * TE_ + (blk & 3) * 2048) + tid;
        float4 v = *p;
        v.x = __expf(v.x - mm) * inv;
        v.y = __expf(v.y - mm) * inv;
        v.z = __expf(v.z - mm) * inv;
        v.w = __expf(v.w - mm) * inv;
        *p = v;
    } else {
        int b = blk - 128;
        batch_stats(b, tid, st);
        __syncthreads();
        if (tid < TPB) sc[tid] = __expf(g_tmax[b * TPB + tid] - st[0]);
        __syncthreads();
        int g = tid >> 7, h = tid & 127;
        float s = 0.f;
#pragma unroll
        for (int j = 0; j < 16; ++j) {
            int ti = g * 16 + j;
            s += g_cpart[(size_t)(b * TPB + ti) * 128 + h] * sc[ti];
        }
        cpz[tid] = s;
        __syncthreads();
        if (tid < 128)
            c_out[b * H_ + tid] =
                (cpz[tid] + cpz[128 + tid] + cpz[256 + tid] + cpz[384 + tid]) * st[1];
    }
}

// ---------------- launch ----------------
extern "C" void kernel_launch(void* const* d_in, const int* in_sizes, int n_in,
                              void* d_out, int out_size) {
    const float* enc = (const float*)d_in[0];
    const float* dec = (const float*)d_in[1];
    const float* W   = (const float*)d_in[2];
    const float* U   = (const float*)d_in[3];
    const float* V   = (const float*)d_in[4];

    float* out   = (float*)d_out;
    float* e_out = out;                        // [B, TE]
    float* c_out = out + (size_t)B_ * TE_;     // [B, H]

    static int s_grid = 0;
    if (!s_grid) {
        int dev = 0, sms = 148;
        cudaGetDevice(&dev);
        cudaDeviceGetAttribute(&sms, cudaDevAttrMultiProcessorCount, dev);
        cudaFuncSetAttribute(k2_scores, cudaFuncAttributeMaxDynamicSharedMemorySize, K2_SMEM);
        s_grid = sms > 0 ? sms : 148;
        if (s_grid > NTILE) s_grid = NTILE;
    }

    k01_prep<<<80, 256>>>(W, dec, U, s_grid);
    k2_scores<<<s_grid, 512, K2_SMEM>>>(enc, V, e_out);
    k45_final<<<160, 512>>>(e_out, c_out);
}

// round 15
// speedup vs baseline: 1.0924x; 1.0924x over previous
#include <cuda_runtime.h>
#include <cuda_bf16.h>
#include <math.h>
#include <stdint.h>

#define B_  32
#define TE_ 8192
#define H_  128
#define NTILE 2048            // (B_*TE_)/128 tiles of 128 timesteps
#define TPB   64              // tiles per batch

// ---------------- device scratch ----------------
__device__ float g_Uh[B_ * H_];
__device__ float g_tmax[NTILE];            // per-tile max
__device__ float g_tsum[NTILE];            // per-tile sum(exp(s - tmax))
__device__ float g_cpart[NTILE * H_];      // exp-weighted partial contexts
__device__ __nv_bfloat16 g_WhiT[H_ * H_];  // W^T split-high [n][h]
__device__ __nv_bfloat16 g_WloT[H_ * H_];  // W^T split-low  [n][h]

// ---------------- helpers ----------------
__device__ __forceinline__ uint32_t smem_u32(const void* p) {
    uint32_t a;
    asm("{ .reg .u64 t; cvta.to.shared.u64 t, %1; cvt.u32.u64 %0, t; }" : "=r"(a) : "l"(p));
    return a;
}
__device__ __forceinline__ void ldsm_x4(uint32_t& r0, uint32_t& r1, uint32_t& r2,
                                        uint32_t& r3, uint32_t addr) {
    asm volatile("ldmatrix.sync.aligned.m8n8.x4.shared.b16 {%0,%1,%2,%3}, [%4];"
                 : "=r"(r0), "=r"(r1), "=r"(r2), "=r"(r3) : "r"(addr));
}
__device__ __forceinline__ void mma_bf16(float* c, uint32_t a0, uint32_t a1,
                                         uint32_t a2, uint32_t a3,
                                         uint32_t b0, uint32_t b1) {
    asm volatile(
        "mma.sync.aligned.m16n8k16.row.col.f32.bf16.bf16.f32 "
        "{%0,%1,%2,%3}, {%4,%5,%6,%7}, {%8,%9}, {%0,%1,%2,%3};"
        : "+f"(c[0]), "+f"(c[1]), "+f"(c[2]), "+f"(c[3])
        : "r"(a0), "r"(a1), "r"(a2), "r"(a3), "r"(b0), "r"(b1));
}
__device__ __forceinline__ float tanh_approx(float x) {
    float y;
    asm("tanh.approx.f32 %0, %1;" : "=f"(y) : "f"(x));
    return y;
}
#define CP_ASYNC16(dst, src) \
    asm volatile("cp.async.cg.shared.global [%0], [%1], 16;" :: "r"(dst), "l"(src))
#define CP_COMMIT()  asm volatile("cp.async.commit_group;" ::: "memory")
#define CP_WAIT0()   asm volatile("cp.async.wait_group 0;" ::: "memory")

// pack hi16(a),hi16(b) -> {lo half = a.hi16, hi half = b.hi16}
__device__ __forceinline__ uint32_t prmt_hi(uint32_t a, uint32_t b) {
    uint32_t d;
    asm("prmt.b32 %0, %1, %2, 0x7632;" : "=r"(d) : "r"(a), "r"(b));
    return d;
}
// pack bf16(lo0) low half, bf16(lo1) high half
__device__ __forceinline__ uint32_t cvt_bf16x2(float lo1, float lo0) {
    uint32_t d;
    asm("cvt.rn.bf16x2.f32 %0, %1, %2;" : "=r"(d) : "f"(lo1), "f"(lo0));
    return d;
}
// split one fp32 pair into packed bf16x2 hi (truncated) and lo (exact residual)
__device__ __forceinline__ void split2(float fx, float fy, uint32_t& hi, uint32_t& lo) {
    uint32_t ux = __float_as_uint(fx), uy = __float_as_uint(fy);
    hi = prmt_hi(ux, uy);
    float lx = fx - __uint_as_float(ux & 0xFFFF0000u);
    float ly = fy - __uint_as_float(uy & 0xFFFF0000u);
    lo = cvt_bf16x2(ly, lx);
}

// ---------------- K01: W^T hi/lo split (blocks 0..63) + Uh (blocks 64..95) ----------------
__global__ void k01_prep(const float* __restrict__ W, const float* __restrict__ dec,
                         const float* __restrict__ U) {
    int bid = blockIdx.x, tid = threadIdx.x;
    if (bid < 64) {
        int idx = bid * 256 + tid;          // 16384 total
        int k = idx >> 7, h = idx & 127;
        float x = W[h * H_ + k];
        __nv_bfloat16 hi = __float2bfloat16(x);
        __nv_bfloat16 lo = __float2bfloat16(x - __bfloat162float(hi));
        g_WhiT[k * H_ + h] = hi;
        g_WloT[k * H_ + h] = lo;
    } else {
        __shared__ float part[256];
        int b = bid - 64;                   // 0..31
        int k = tid & 127, half = tid >> 7;
        const float* Up = U + (half * 64) * H_ + k;
        const float* dp = dec + b * H_ + half * 64;
        float acc = 0.f;
#pragma unroll
        for (int h = 0; h < 64; ++h) acc = fmaf(dp[h], Up[h * H_], acc);
        part[tid] = acc;
        __syncthreads();
        if (half == 0) g_Uh[b * H_ + k] = part[k] + part[128 + k];
    }
}

// ---------------- K2: persistent fused GEMM + tanh·V + online softmax + context ----------------
#define RSTR     272                      // B tiles: 128 bf16 + 8 pad = 272 B rows
#define SROW     544                      // stage rows: 136 words (conflict-free frag LDS)
#define OFF_V    0
#define OFF_EPI  512
#define OFF_SW   1536
#define OFF_RED  2048
#define OFF_UHS  2112
#define OFF_CP   2624                     // 8 x 128 floats
#define OFF_BHI  6720
#define OFF_BLO  (OFF_BHI + 128 * RSTR)   // 41536
#define OFF_STG0 (OFF_BLO + 128 * RSTR)   // 76352
#define OFF_STG1 (OFF_STG0 + 128 * SROW)  // 145984
#define K2_SMEM  (OFF_STG1 + 128 * SROW)  // 215616 B

__global__ void __launch_bounds__(512, 1)
k2_scores(const float* __restrict__ enc, const float* __restrict__ V,
          float* __restrict__ scores) {
    extern __shared__ char sm[];
    uint32_t base = smem_u32(sm);

    int tid  = threadIdx.x;
    int wid  = tid >> 5;
    int lane = tid & 31;

    float* v_s  = (float*)(sm + OFF_V);
    float* epi  = (float*)(sm + OFF_EPI);
    float* swm  = (float*)(sm + OFF_SW);
    float* red  = (float*)(sm + OFF_RED);
    float* uh_s = (float*)(sm + OFF_UHS);
    float* cp   = (float*)(sm + OFF_CP);

    if (tid < 128) v_s[tid] = V[tid];

    // W tiles: loaded ONCE per CTA
#pragma unroll
    for (int i = 0; i < 8; ++i) {
        int g = i * 512 + tid;
        int row = g >> 5, c = g & 31;
        int off = row * RSTR + c * 8;
        *(uint2*)(sm + OFF_BHI + off) = *(const uint2*)(g_WhiT + row * 128 + c * 4);
        *(uint2*)(sm + OFF_BLO + off) = *(const uint2*)(g_WloT + row * 128 + c * 4);
    }

    int wy = wid & 7, wx = wid >> 3;       // 16 rows x 64 cols per warp
    uint32_t bOff = (uint32_t)(((lane & 7) + ((lane >> 4) << 3)) * RSTR + (((lane >> 3) & 1) << 4));
    uint32_t bHi = base + OFF_BHI + wx * 64 * RSTR + bOff;
    uint32_t bLo = base + OFF_BLO + wx * 64 * RSTR + bOff;
    // per-thread A-fragment base offset within a stage buffer
    uint32_t aFrag = (uint32_t)((wy * 16 + (lane >> 2)) * SROW + (lane & 3) * 8);
    uint32_t stgAddr[2] = { base + OFF_STG0, base + OFF_STG1 };
    const char* stgPtr[2] = { sm + OFF_STG0, sm + OFF_STG1 };

    int T = blockIdx.x;
    int cur = 0;
    if (T < NTILE) {
        const float4* encT = (const float4*)(enc + (size_t)T * 128 * H_);
        uint32_t dstb = stgAddr[0];
#pragma unroll
        for (int i = 0; i < 8; ++i) {
            int g = i * 512 + tid;
            int row = g >> 5, cch = g & 31;
            CP_ASYNC16(dstb + row * SROW + cch * 16, encT + g);
        }
        CP_COMMIT();
    }

    while (T < NTILE) {
        int b = T >> 6;
        if (tid < 128) uh_s[tid] = g_Uh[b * 128 + tid];

        CP_WAIT0();
        __syncthreads();   // stage[cur] ready; uh_s visible; prev-tile smem free

        // prefetch NEXT tile into the other stage buffer (overlaps everything below)
        int Tn = T + gridDim.x;
        if (Tn < NTILE) {
            const float4* encT = (const float4*)(enc + (size_t)Tn * 128 * H_);
            uint32_t dstb = stgAddr[cur ^ 1];
#pragma unroll
            for (int i = 0; i < 8; ++i) {
                int g = i * 512 + tid;
                int row = g >> 5, cch = g & 31;
                CP_ASYNC16(dstb + row * SROW + cch * 16, encT + g);
            }
        }
        CP_COMMIT();

        // ---- MMA: A fragments generated in registers from fp32 stage
        const char* aB = stgPtr[cur] + aFrag;
        float c[8][4];
#pragma unroll
        for (int n = 0; n < 8; ++n)
#pragma unroll
            for (int j = 0; j < 4; ++j) c[n][j] = 0.f;

#pragma unroll
        for (int k = 0; k < 8; ++k) {
            uint32_t kb = k * 32;
            uint32_t bh[4][4], bl[4][4];
#pragma unroll
            for (int p = 0; p < 4; ++p) {
                ldsm_x4(bh[p][0], bh[p][1], bh[p][2], bh[p][3], bHi + p * 16 * RSTR + kb);
                ldsm_x4(bl[p][0], bl[p][1], bl[p][2], bl[p][3], bLo + p * 16 * RSTR + kb);
            }
            // A: 4 fp32 pairs -> hi/lo fragments
            float2 p00 = *(const float2*)(aB + k * 64);
            float2 p10 = *(const float2*)(aB + k * 64 + 8 * SROW);
            float2 p01 = *(const float2*)(aB + k * 64 + 32);
            float2 p11 = *(const float2*)(aB + k * 64 + 8 * SROW + 32);
            uint32_t ah0, ah1, ah2, ah3, al0, al1, al2, al3;
            split2(p00.x, p00.y, ah0, al0);
            split2(p10.x, p10.y, ah1, al1);
            split2(p01.x, p01.y, ah2, al2);
            split2(p11.x, p11.y, ah3, al3);
#pragma unroll
            for (int p = 0; p < 4; ++p) {
                mma_bf16(c[2 * p],     ah0, ah1, ah2, ah3, bh[p][0], bh[p][1]);
                mma_bf16(c[2 * p + 1], ah0, ah1, ah2, ah3, bh[p][2], bh[p][3]);
                mma_bf16(c[2 * p],     ah0, ah1, ah2, ah3, bl[p][0], bl[p][1]);
                mma_bf16(c[2 * p + 1], ah0, ah1, ah2, ah3, bl[p][2], bl[p][3]);
                mma_bf16(c[2 * p],     al0, al1, al2, al3, bh[p][0], bh[p][1]);
                mma_bf16(c[2 * p + 1], al0, al1, al2, al3, bh[p][2], bh[p][3]);
            }
        }

        // ---- epilogue: s[t] = sum_n v[n] * tanh(y + uh[n])
        {
            int qid = lane >> 2;
            int npair = (lane & 3) * 2;
            float s0 = 0.f, s1 = 0.f;
#pragma unroll
            for (int nt = 0; nt < 8; ++nt) {
                int n = wx * 64 + nt * 8 + npair;
                float vn0 = v_s[n], vn1 = v_s[n + 1];
                float u0 = uh_s[n], u1 = uh_s[n + 1];
                s0 += vn0 * tanh_approx(c[nt][0] + u0) + vn1 * tanh_approx(c[nt][1] + u1);
                s1 += vn0 * tanh_approx(c[nt][2] + u0) + vn1 * tanh_approx(c[nt][3] + u1);
            }
            s0 += __shfl_xor_sync(0xffffffffu, s0, 1);
            s0 += __shfl_xor_sync(0xffffffffu, s0, 2);
            s1 += __shfl_xor_sync(0xffffffffu, s1, 1);
            s1 += __shfl_xor_sync(0xffffffffu, s1, 2);
            if ((lane & 3) == 0) {
                int r = wy * 16 + qid;
                epi[wx * 128 + r]     = s0;
                epi[wx * 128 + r + 8] = s1;
            }
        }
        __syncthreads();

        // ---- tile softmax stats
        float sv = 0.f;
        if (tid < 128) {
            sv = epi[tid] + epi[128 + tid];
            scores[(size_t)T * 128 + tid] = sv;
            float m = sv;
#pragma unroll
            for (int msk = 16; msk; msk >>= 1) m = fmaxf(m, __shfl_xor_sync(0xffffffffu, m, msk));
            if (lane == 0) red[wid] = m;
        }
        __syncthreads();
        float mt = fmaxf(fmaxf(red[0], red[1]), fmaxf(red[2], red[3]));
        if (tid < 128) {
            float w = __expf(sv - mt);
            swm[tid] = w;
#pragma unroll
            for (int msk = 16; msk; msk >>= 1) w += __shfl_xor_sync(0xffffffffu, w, msk);
            if (lane == 0) red[4 + wid] = w;
        }
        __syncthreads();
        if (tid == 0) {
            g_tmax[T] = mt;
            g_tsum[T] = red[4] + red[5] + red[6] + red[7];
        }

        // ---- partial context straight from fp32 stage: cpart[h] = sum_t w[t]*enc[t][h]
        {
            int hp2 = tid & 63;               // h-pair
            int sl  = tid >> 6;               // 8 slices of 16 timesteps
            const char* pS = stgPtr[cur] + (sl * 16) * SROW + hp2 * 8;
            float ax = 0.f, ay = 0.f;
#pragma unroll
            for (int t = 0; t < 16; ++t) {
                float2 v = *(const float2*)(pS + t * SROW);
                float w = swm[sl * 16 + t];
                ax = fmaf(w, v.x, ax);
                ay = fmaf(w, v.y, ay);
            }
            cp[sl * 128 + hp2 * 2]     = ax;
            cp[sl * 128 + hp2 * 2 + 1] = ay;
        }
        __syncthreads();
        if (tid < 128) {
            float s = 0.f;
#pragma unroll
            for (int sl = 0; sl < 8; ++sl) s += cp[sl * 128 + tid];
            g_cpart[(size_t)T * 128 + tid] = s;
        }

        T = Tn;
        cur ^= 1;
    }
}

// ---------------- batch stats helper (warp 0 computes mm, inv) ----------------
__device__ __forceinline__ void batch_stats(int b, int tid, float* s_out) {
    if (tid < 32) {
        float m0 = g_tmax[b * TPB + tid], m1 = g_tmax[b * TPB + 32 + tid];
        float mm = fmaxf(m0, m1);
#pragma unroll
        for (int msk = 16; msk; msk >>= 1) mm = fmaxf(mm, __shfl_xor_sync(0xffffffffu, mm, msk));
        float s = g_tsum[b * TPB + tid] * __expf(m0 - mm)
                + g_tsum[b * TPB + 32 + tid] * __expf(m1 - mm);
#pragma unroll
        for (int msk = 16; msk; msk >>= 1) s += __shfl_xor_sync(0xffffffffu, s, msk);
        if (tid == 0) { s_out[0] = mm; s_out[1] = 1.f / s; }
    }
}

// ---------------- K45: blocks 0..127 normalize e; blocks 128..159 reduce contexts ----------------
__global__ void __launch_bounds__(512)
k45_final(float* __restrict__ e_out, float* __restrict__ c_out) {
    __shared__ float st[2];
    __shared__ float sc[TPB];
    __shared__ float cpz[4 * 128];
    int blk = blockIdx.x, tid = threadIdx.x;

    if (blk < 128) {
        int b = blk >> 2;
        batch_stats(b, tid, st);
        __syncthreads();
        float mm = st[0], inv = st[1];
        float4* p = (float4*)(e_out + (size_t)b * TE_ + (blk & 3) * 2048) + tid;
        float4 v = *p;
        v.x = __expf(v.x - mm) * inv;
        v.y = __expf(v.y - mm) * inv;
        v.z = __expf(v.z - mm) * inv;
        v.w = __expf(v.w - mm) * inv;
        *p = v;
    } else {
        int b = blk - 128;
        batch_stats(b, tid, st);
        __syncthreads();
        if (tid < TPB) sc[tid] = __expf(g_tmax[b * TPB + tid] - st[0]);
        __syncthreads();
        int g = tid >> 7, h = tid & 127;
        float s = 0.f;
#pragma unroll
        for (int j = 0; j < 16; ++j) {
            int ti = g * 16 + j;
            s += g_cpart[(size_t)(b * TPB + ti) * 128 + h] * sc[ti];
        }
        cpz[tid] = s;
        __syncthreads();
        if (tid < 128)
            c_out[b * H_ + tid] =
                (cpz[tid] + cpz[128 + tid] + cpz[256 + tid] + cpz[384 + tid]) * st[1];
    }
}

// ---------------- launch ----------------
extern "C" void kernel_launch(void* const* d_in, const int* in_sizes, int n_in,
                              void* d_out, int out_size) {
    const float* enc = (const float*)d_in[0];
    const float* dec = (const float*)d_in[1];
    const float* W   = (const float*)d_in[2];
    const float* U   = (const float*)d_in[3];
    const float* V   = (const float*)d_in[4];

    float* out   = (float*)d_out;
    float* e_out = out;                        // [B, TE]
    float* c_out = out + (size_t)B_ * TE_;     // [B, H]

    static int s_grid = 0;
    if (!s_grid) {
        int dev = 0, sms = 148;
        cudaGetDevice(&dev);
        cudaDeviceGetAttribute(&sms, cudaDevAttrMultiProcessorCount, dev);
        cudaFuncSetAttribute(k2_scores, cudaFuncAttributeMaxDynamicSharedMemorySize, K2_SMEM);
        s_grid = sms > 0 ? sms : 148;
        if (s_grid > NTILE) s_grid = NTILE;
    }

    k01_prep<<<96, 256>>>(W, dec, U);
    k2_scores<<<s_grid, 512, K2_SMEM>>>(enc, V, e_out);
    k45_final<<<160, 512>>>(e_out, c_out);
}

// round 16
// speedup vs baseline: 1.2194x; 1.1162x over previous
#include <cuda_runtime.h>
#include <cuda_bf16.h>
#include <math.h>
#include <stdint.h>

#define B_  32
#define TE_ 8192
#define H_  128
#define NTILE 2048            // (B_*TE_)/128 tiles of 128 timesteps
#define TPB   64              // tiles per batch

// ---------------- device scratch ----------------
__device__ float g_Uh[B_ * H_];
__device__ float g_tmax[NTILE];            // per-tile max
__device__ float g_tsum[NTILE];            // per-tile sum(exp(s - tmax))
__device__ float g_cpart[NTILE * H_];      // exp-weighted partial contexts
__device__ int g_uhcnt;                    // Uh producer counter (monotonic)

// ---------------- helpers ----------------
__device__ __forceinline__ uint32_t smem_u32(const void* p) {
    uint32_t a;
    asm("{ .reg .u64 t; cvta.to.shared.u64 t, %1; cvt.u32.u64 %0, t; }" : "=r"(a) : "l"(p));
    return a;
}
__device__ __forceinline__ void ldsm_x4(uint32_t& r0, uint32_t& r1, uint32_t& r2,
                                        uint32_t& r3, uint32_t addr) {
    asm volatile("ldmatrix.sync.aligned.m8n8.x4.shared.b16 {%0,%1,%2,%3}, [%4];"
                 : "=r"(r0), "=r"(r1), "=r"(r2), "=r"(r3) : "r"(addr));
}
__device__ __forceinline__ void mma_bf16(float* c, uint32_t a0, uint32_t a1,
                                         uint32_t a2, uint32_t a3,
                                         uint32_t b0, uint32_t b1) {
    asm volatile(
        "mma.sync.aligned.m16n8k16.row.col.f32.bf16.bf16.f32 "
        "{%0,%1,%2,%3}, {%4,%5,%6,%7}, {%8,%9}, {%0,%1,%2,%3};"
        : "+f"(c[0]), "+f"(c[1]), "+f"(c[2]), "+f"(c[3])
        : "r"(a0), "r"(a1), "r"(a2), "r"(a3), "r"(b0), "r"(b1));
}
__device__ __forceinline__ float tanh_approx(float x) {
    float y;
    asm("tanh.approx.f32 %0, %1;" : "=f"(y) : "f"(x));
    return y;
}
#define CP_ASYNC16(dst, src) \
    asm volatile("cp.async.cg.shared.global [%0], [%1], 16;" :: "r"(dst), "l"(src))
#define CP_COMMIT()  asm volatile("cp.async.commit_group;" ::: "memory")
#define CP_WAIT0()   asm volatile("cp.async.wait_group 0;" ::: "memory")

// pack hi16(a),hi16(b) -> {lo half = a.hi16, hi half = b.hi16}
__device__ __forceinline__ uint32_t prmt_hi(uint32_t a, uint32_t b) {
    uint32_t d;
    asm("prmt.b32 %0, %1, %2, 0x7632;" : "=r"(d) : "r"(a), "r"(b));
    return d;
}
// pack bf16(lo0) low half, bf16(lo1) high half
__device__ __forceinline__ uint32_t cvt_bf16x2(float lo1, float lo0) {
    uint32_t d;
    asm("cvt.rn.bf16x2.f32 %0, %1, %2;" : "=r"(d) : "f"(lo1), "f"(lo0));
    return d;
}
// split one fp32 pair into packed bf16x2 hi (truncated) and lo (exact residual)
__device__ __forceinline__ void split2(float fx, float fy, uint32_t& hi, uint32_t& lo) {
    uint32_t ux = __float_as_uint(fx), uy = __float_as_uint(fy);
    hi = prmt_hi(ux, uy);
    float lx = fx - __uint_as_float(ux & 0xFFFF0000u);
    float ly = fy - __uint_as_float(uy & 0xFFFF0000u);
    lo = cvt_bf16x2(ly, lx);
}

// ---------------- K2: persistent, self-contained ----------------
#define RSTR     272                      // B tiles: 128 bf16 + 8 pad = 272 B rows
#define SROW     544                      // stage rows: 136 words (conflict-free frag LDS)
#define OFF_V    0
#define OFF_EPI  512
#define OFF_SW   1536
#define OFF_RED  2048
#define OFF_UHS  2112
#define OFF_CP   2624                     // 8 x 128 floats
#define OFF_BHI  6720
#define OFF_BLO  (OFF_BHI + 128 * RSTR)   // 41536
#define OFF_STG0 (OFF_BLO + 128 * RSTR)   // 76352
#define OFF_STG1 (OFF_STG0 + 128 * SROW)  // 145984
#define K2_SMEM  (OFF_STG1 + 128 * SROW)  // 215616 B

__global__ void __launch_bounds__(512, 1)
k2_scores(const float* __restrict__ enc, const float* __restrict__ dec,
          const float* __restrict__ W, const float* __restrict__ U,
          const float* __restrict__ V, float* __restrict__ scores) {
    extern __shared__ char sm[];
    uint32_t base = smem_u32(sm);

    int tid  = threadIdx.x;
    int wid  = tid >> 5;
    int lane = tid & 31;
    int bid  = blockIdx.x;

    float* v_s  = (float*)(sm + OFF_V);
    float* epi  = (float*)(sm + OFF_EPI);
    float* swm  = (float*)(sm + OFF_SW);
    float* red  = (float*)(sm + OFF_RED);
    float* uh_s = (float*)(sm + OFF_UHS);
    float* cp   = (float*)(sm + OFF_CP);
    const float* stg1f = (const float*)(sm + OFF_STG1);

    if (tid < 128) v_s[tid] = V[tid];

    uint32_t stgAddr[2] = { base + OFF_STG0, base + OFF_STG1 };
    const char* stgPtr[2] = { sm + OFF_STG0, sm + OFF_STG1 };

    // --- issue cp.async: enc tile T0 -> stg0, raw W -> stg1 (one group)
    int T = bid;
    if (T < NTILE) {
        const float4* encT = (const float4*)(enc + (size_t)T * 128 * H_);
        const float4* Wv   = (const float4*)W;
#pragma unroll
        for (int i = 0; i < 8; ++i) {
            int g = i * 512 + tid;
            int row = g >> 5, cch = g & 31;
            CP_ASYNC16(stgAddr[0] + row * SROW + cch * 16, encT + g);
            CP_ASYNC16(stgAddr[1] + row * SROW + cch * 16, Wv + g);
        }
        CP_COMMIT();
    }

    // --- producer CTAs 0..31: Uh[bid] = dec[bid] @ U (overlaps the cp.async)
    if (bid < 32) {
        int k = tid & 127, q = tid >> 7;
        const float* Up = U + (q * 32) * H_ + k;
        const float* dp = dec + bid * H_ + q * 32;
        float acc = 0.f;
#pragma unroll
        for (int h = 0; h < 32; ++h) acc = fmaf(dp[h], Up[h * H_], acc);
        cp[q * 128 + k] = acc;
        __syncthreads();
        if (tid < 128)
            g_Uh[bid * H_ + tid] = cp[tid] + cp[128 + tid] + cp[256 + tid] + cp[384 + tid];
        __threadfence();
        __syncthreads();
        if (tid == 0) atomicAdd(&g_uhcnt, 1);
    }

    CP_WAIT0();
    __syncthreads();

    // --- build B hi/lo tiles from raw W in stg1:  B[n][h] = split(W[h][n])
    {
        int n = tid & 127;
        int hpBase = (tid >> 7) * 16;        // 16 h-pairs per thread
#pragma unroll
        for (int j = 0; j < 16; ++j) {
            int hp = hpBase + j, h = hp * 2;
            float x0 = stg1f[h * 136 + n];
            float x1 = stg1f[(h + 1) * 136 + n];
            __nv_bfloat16 h0 = __float2bfloat16(x0);
            __nv_bfloat16 h1 = __float2bfloat16(x1);
            float l0 = x0 - __bfloat162float(h0);
            float l1 = x1 - __bfloat162float(h1);
            uint32_t hpk = (uint32_t)__bfloat16_as_ushort(h0)
                         | ((uint32_t)__bfloat16_as_ushort(h1) << 16);
            uint32_t lpk = cvt_bf16x2(l1, l0);
            int off = n * RSTR + hp * 4;
            *(uint32_t*)(sm + OFF_BHI + off) = hpk;
            *(uint32_t*)(sm + OFF_BLO + off) = lpk;
        }
    }

    // --- wait for all Uh producers (once; replays skip instantly)
    if (tid == 0) {
        int v;
        do { asm volatile("ld.acquire.gpu.s32 %0, [%1];" : "=r"(v) : "l"(&g_uhcnt)); }
        while (v < 32);
    }
    __syncthreads();   // B tiles built + Uh ready

    int wy = wid & 7, wx = wid >> 3;       // 16 rows x 64 cols per warp
    uint32_t bOff = (uint32_t)(((lane & 7) + ((lane >> 4) << 3)) * RSTR + (((lane >> 3) & 1) << 4));
    uint32_t bHi = base + OFF_BHI + wx * 64 * RSTR + bOff;
    uint32_t bLo = base + OFF_BLO + wx * 64 * RSTR + bOff;
    uint32_t aFrag = (uint32_t)((wy * 16 + (lane >> 2)) * SROW + (lane & 3) * 8);

    int cur = 0;
    while (T < NTILE) {
        int b = T >> 6;
        if (tid < 128) uh_s[tid] = g_Uh[b * 128 + tid];

        // prefetch NEXT tile into the other stage buffer
        int Tn = T + gridDim.x;
        if (Tn < NTILE) {
            const float4* encT = (const float4*)(enc + (size_t)Tn * 128 * H_);
            uint32_t dstb = stgAddr[cur ^ 1];
#pragma unroll
            for (int i = 0; i < 8; ++i) {
                int g = i * 512 + tid;
                int row = g >> 5, cch = g & 31;
                CP_ASYNC16(dstb + row * SROW + cch * 16, encT + g);
            }
        }
        CP_COMMIT();

        // ---- MMA: A fragments generated in registers from fp32 stage
        const char* aB = stgPtr[cur] + aFrag;
        float c[8][4];
#pragma unroll
        for (int n = 0; n < 8; ++n)
#pragma unroll
            for (int j = 0; j < 4; ++j) c[n][j] = 0.f;

#pragma unroll
        for (int k = 0; k < 8; ++k) {
            uint32_t kb = k * 32;
            uint32_t bh[4][4], bl[4][4];
#pragma unroll
            for (int p = 0; p < 4; ++p) {
                ldsm_x4(bh[p][0], bh[p][1], bh[p][2], bh[p][3], bHi + p * 16 * RSTR + kb);
                ldsm_x4(bl[p][0], bl[p][1], bl[p][2], bl[p][3], bLo + p * 16 * RSTR + kb);
            }
            float2 p00 = *(const float2*)(aB + k * 64);
            float2 p10 = *(const float2*)(aB + k * 64 + 8 * SROW);
            float2 p01 = *(const float2*)(aB + k * 64 + 32);
            float2 p11 = *(const float2*)(aB + k * 64 + 8 * SROW + 32);
            uint32_t ah0, ah1, ah2, ah3, al0, al1, al2, al3;
            split2(p00.x, p00.y, ah0, al0);
            split2(p10.x, p10.y, ah1, al1);
            split2(p01.x, p01.y, ah2, al2);
            split2(p11.x, p11.y, ah3, al3);
#pragma unroll
            for (int p = 0; p < 4; ++p) {
                mma_bf16(c[2 * p],     ah0, ah1, ah2, ah3, bh[p][0], bh[p][1]);
                mma_bf16(c[2 * p + 1], ah0, ah1, ah2, ah3, bh[p][2], bh[p][3]);
                mma_bf16(c[2 * p],     ah0, ah1, ah2, ah3, bl[p][0], bl[p][1]);
                mma_bf16(c[2 * p + 1], ah0, ah1, ah2, ah3, bl[p][2], bl[p][3]);
                mma_bf16(c[2 * p],     al0, al1, al2, al3, bh[p][0], bh[p][1]);
                mma_bf16(c[2 * p + 1], al0, al1, al2, al3, bh[p][2], bh[p][3]);
            }
        }

        // ---- epilogue: s[t] = sum_n v[n] * tanh(y + uh[n])
        {
            int qid = lane >> 2;
            int npair = (lane & 3) * 2;
            float s0 = 0.f, s1 = 0.f;
#pragma unroll
            for (int nt = 0; nt < 8; ++nt) {
                int n = wx * 64 + nt * 8 + npair;
                float vn0 = v_s[n], vn1 = v_s[n + 1];
                float u0 = uh_s[n], u1 = uh_s[n + 1];
                s0 += vn0 * tanh_approx(c[nt][0] + u0) + vn1 * tanh_approx(c[nt][1] + u1);
                s1 += vn0 * tanh_approx(c[nt][2] + u0) + vn1 * tanh_approx(c[nt][3] + u1);
            }
            s0 += __shfl_xor_sync(0xffffffffu, s0, 1);
            s0 += __shfl_xor_sync(0xffffffffu, s0, 2);
            s1 += __shfl_xor_sync(0xffffffffu, s1, 1);
            s1 += __shfl_xor_sync(0xffffffffu, s1, 2);
            if ((lane & 3) == 0) {
                int r = wy * 16 + qid;
                epi[wx * 128 + r]     = s0;
                epi[wx * 128 + r + 8] = s1;
            }
        }
        __syncthreads();

        // ---- tile softmax stats
        float sv = 0.f;
        if (tid < 128) {
            sv = epi[tid] + epi[128 + tid];
            scores[(size_t)T * 128 + tid] = sv;
            float m = sv;
#pragma unroll
            for (int msk = 16; msk; msk >>= 1) m = fmaxf(m, __shfl_xor_sync(0xffffffffu, m, msk));
            if (lane == 0) red[wid] = m;
        }
        __syncthreads();
        float mt = fmaxf(fmaxf(red[0], red[1]), fmaxf(red[2], red[3]));
        if (tid < 128) {
            float w = __expf(sv - mt);
            swm[tid] = w;
#pragma unroll
            for (int msk = 16; msk; msk >>= 1) w += __shfl_xor_sync(0xffffffffu, w, msk);
            if (lane == 0) red[4 + wid] = w;
        }
        __syncthreads();
        if (tid == 0) {
            g_tmax[T] = mt;
            g_tsum[T] = red[4] + red[5] + red[6] + red[7];
        }

        // ---- partial context straight from fp32 stage
        {
            int hp2 = tid & 63;
            int sl  = tid >> 6;               // 8 slices of 16 timesteps
            const char* pS = stgPtr[cur] + (sl * 16) * SROW + hp2 * 8;
            float ax = 0.f, ay = 0.f;
#pragma unroll
            for (int t = 0; t < 16; ++t) {
                float2 v = *(const float2*)(pS + t * SROW);
                float w = swm[sl * 16 + t];
                ax = fmaf(w, v.x, ax);
                ay = fmaf(w, v.y, ay);
            }
            cp[sl * 128 + hp2 * 2]     = ax;
            cp[sl * 128 + hp2 * 2 + 1] = ay;
        }
        __syncthreads();
        if (tid < 128) {
            float s = 0.f;
#pragma unroll
            for (int sl = 0; sl < 8; ++sl) s += cp[sl * 128 + tid];
            g_cpart[(size_t)T * 128 + tid] = s;
        }
        CP_WAIT0();
        __syncthreads();   // next stage ready; this tile's smem reads done

        T = Tn;
        cur ^= 1;
    }
}

// ---------------- batch stats helper (warp 0 computes mm, inv) ----------------
__device__ __forceinline__ void batch_stats(int b, int tid, float* s_out) {
    if (tid < 32) {
        float m0 = g_tmax[b * TPB + tid], m1 = g_tmax[b * TPB + 32 + tid];
        float mm = fmaxf(m0, m1);
#pragma unroll
        for (int msk = 16; msk; msk >>= 1) mm = fmaxf(mm, __shfl_xor_sync(0xffffffffu, mm, msk));
        float s = g_tsum[b * TPB + tid] * __expf(m0 - mm)
                + g_tsum[b * TPB + 32 + tid] * __expf(m1 - mm);
#pragma unroll
        for (int msk = 16; msk; msk >>= 1) s += __shfl_xor_sync(0xffffffffu, s, msk);
        if (tid == 0) { s_out[0] = mm; s_out[1] = 1.f / s; }
    }
}

// ---------------- K45: blocks 0..127 normalize e; blocks 128..159 reduce contexts ----------------
__global__ void __launch_bounds__(512)
k45_final(float* __restrict__ e_out, float* __restrict__ c_out) {
    __shared__ float st[2];
    __shared__ float sc[TPB];
    __shared__ float cpz[4 * 128];
    int blk = blockIdx.x, tid = threadIdx.x;

    if (blk < 128) {
        int b = blk >> 2;
        batch_stats(b, tid, st);
        __syncthreads();
        float mm = st[0], inv = st[1];
        float4* p = (float4*)(e_out + (size_t)b * TE_ + (blk & 3) * 2048) + tid;
        float4 v = *p;
        v.x = __expf(v.x - mm) * inv;
        v.y = __expf(v.y - mm) * inv;
        v.z = __expf(v.z - mm) * inv;
        v.w = __expf(v.w - mm) * inv;
        *p = v;
    } else {
        int b = blk - 128;
        batch_stats(b, tid, st);
        __syncthreads();
        if (tid < TPB) sc[tid] = __expf(g_tmax[b * TPB + tid] - st[0]);
        __syncthreads();
        int g = tid >> 7, h = tid & 127;
        float s = 0.f;
#pragma unroll
        for (int j = 0; j < 16; ++j) {
            int ti = g * 16 + j;
            s += g_cpart[(size_t)(b * TPB + ti) * 128 + h] * sc[ti];
        }
        cpz[tid] = s;
        __syncthreads();
        if (tid < 128)
            c_out[b * H_ + tid] =
                (cpz[tid] + cpz[128 + tid] + cpz[256 + tid] + cpz[384 + tid]) * st[1];
    }
}

// ---------------- launch ----------------
extern "C" void kernel_launch(void* const* d_in, const int* in_sizes, int n_in,
                              void* d_out, int out_size) {
    const float* enc = (const float*)d_in[0];
    const float* dec = (const float*)d_in[1];
    const float* W   = (const float*)d_in[2];
    const float* U   = (const float*)d_in[3];
    const float* V   = (const float*)d_in[4];

    float* out   = (float*)d_out;
    float* e_out = out;                        // [B, TE]
    float* c_out = out + (size_t)B_ * TE_;     // [B, H]

    static int s_grid = 0;
    if (!s_grid) {
        int dev = 0, sms = 148;
        cudaGetDevice(&dev);
        cudaDeviceGetAttribute(&sms, cudaDevAttrMultiProcessorCount, dev);
        cudaFuncSetAttribute(k2_scores, cudaFuncAttributeMaxDynamicSharedMemorySize, K2_SMEM);
        s_grid = sms > 0 ? sms : 148;
        if (s_grid > NTILE) s_grid = NTILE;
        if (s_grid < 32) s_grid = 32;   // Uh producers must all be resident
    }

    k2_scores<<<s_grid, 512, K2_SMEM>>>(enc, dec, W, U, V, e_out);
    k45_final<<<160, 512>>>(e_out, c_out);
}